// round 7
// baseline (speedup 1.0000x reference)
#include <cuda_runtime.h>
#include <cuda_fp16.h>
#include <cuda_bf16.h>
#include <math.h>

// ---------------- problem constants ----------------
#define IN_DIM 256
#define HID 64
#define OUTD 16
#define NEG_SLOPE 0.01f

#define MAXN 50048
#define MAXE 1600000

// ---------------- device scratch (static, no allocs; zero-init at load) ----------------
__device__ __align__(16) __half g_Hw0h[(size_t)MAXN * HID]; // X @ W0 (fp16 for gather)
__device__ __align__(16) __half g_Hw1h[(size_t)MAXN * OUTD];// H @ W1 (fp16 for gather)
__device__ float g_pr0[MAXN], g_pc0[MAXN];
__device__ float g_pr1[MAXN], g_pc1[MAXN];
__device__ __align__(16) int g_cnt[MAXN];   // zero at load; scan re-zeroes each run
__device__ int   g_rowptr[MAXN + 1];
__device__ __align__(16) int g_pos[MAXE];
__device__ int   g_col[MAXE];

// ---------------- packed fp32x2 FMA — register-only packing (no memory punning!) ----------------
__device__ __forceinline__ void ffma2(float2& d, float2 a, float2 b) {
    asm("{\n\t"
        ".reg .b64 ra, rb, rd;\n\t"
        "mov.b64 ra, {%2, %3};\n\t"
        "mov.b64 rb, {%4, %5};\n\t"
        "mov.b64 rd, {%0, %1};\n\t"
        "fma.rn.f32x2 rd, ra, rb, rd;\n\t"
        "mov.b64 {%0, %1}, rd;\n\t"
        "}"
        : "+f"(d.x), "+f"(d.y)
        : "f"(a.x), "f"(a.y), "f"(b.x), "f"(b.y));
}

// ---------------- tf32 MMA helpers ----------------
__device__ __forceinline__ float f32_mask13(float x) {
    return __uint_as_float(__float_as_uint(x) & 0xFFFFE000u);
}
__device__ __forceinline__ void mma_tf32(float d[4], const float a[4], float b0, float b1) {
    asm volatile(
        "mma.sync.aligned.m16n8k8.row.col.f32.tf32.tf32.f32 "
        "{%0,%1,%2,%3}, {%4,%5,%6,%7}, {%8,%9}, {%0,%1,%2,%3};\n"
        : "+f"(d[0]), "+f"(d[1]), "+f"(d[2]), "+f"(d[3])
        : "r"(__float_as_uint(a[0])), "r"(__float_as_uint(a[1])),
          "r"(__float_as_uint(a[2])), "r"(__float_as_uint(a[3])),
          "r"(__float_as_uint(b0)), "r"(__float_as_uint(b1)));
}

// ---------------- FAT kernel: count_pos blocks + gemm0 blocks ----------------
#define GBM 128
#define EDGES_PER_BLK 1024

__global__ __launch_bounds__(128) void fat_kernel(
    const float* __restrict__ X, const float* __restrict__ W,
    const float* __restrict__ a0, const int* __restrict__ ei,
    int M, int E, int nCountBlks)
{
    __shared__ float As[GBM][36];
    __shared__ float Bs[32][64];
    __shared__ float Bl[32][64];

    int tid = threadIdx.x;

    if ((int)blockIdx.x < nCountBlks) {
        int base = blockIdx.x * EDGES_PER_BLK;
        #pragma unroll
        for (int h = 0; h < 2; h++) {
            int e = base + h * 512 + tid * 4;
            if (e + 3 < E) {
                int4 r = *(const int4*)(ei + e);
                int4 p;
                p.x = atomicAdd(&g_cnt[r.x], 1);
                p.y = atomicAdd(&g_cnt[r.y], 1);
                p.z = atomicAdd(&g_cnt[r.z], 1);
                p.w = atomicAdd(&g_cnt[r.w], 1);
                *(int4*)(g_pos + e) = p;
            } else {
                for (int j = e; j < E; j++) g_pos[j] = atomicAdd(&g_cnt[ei[j]], 1);
            }
        }
        return;
    }

    int lane = tid & 31, warp = tid >> 5;
    int gid = lane >> 2, tig = lane & 3;
    int block_m = (blockIdx.x - nCountBlks) * GBM;

    float d[2][8][4];
    #pragma unroll
    for (int mt = 0; mt < 2; mt++)
        #pragma unroll
        for (int nt = 0; nt < 8; nt++)
            #pragma unroll
            for (int q = 0; q < 4; q++) d[mt][nt][q] = 0.f;

    for (int k0 = 0; k0 < IN_DIM; k0 += 32) {
        #pragma unroll
        for (int i = 0; i < 8; i++) {
            int f = tid + 128 * i;
            int row = f >> 3, q = (f & 7) * 4;
            int gm = block_m + row;
            float4 v = (gm < M) ? *(const float4*)(X + (size_t)gm * IN_DIM + k0 + q)
                                : make_float4(0.f, 0.f, 0.f, 0.f);
            *(float4*)&As[row][q] = v;
        }
        #pragma unroll
        for (int i = 0; i < 4; i++) {
            int f = tid + 128 * i;
            int k = f >> 4, nq = (f & 15) * 4;
            float4 v = *(const float4*)(W + (size_t)(k0 + k) * HID + nq);
            float4 l;
            l.x = v.x - f32_mask13(v.x);
            l.y = v.y - f32_mask13(v.y);
            l.z = v.z - f32_mask13(v.z);
            l.w = v.w - f32_mask13(v.w);
            *(float4*)&Bs[k][nq] = v;
            *(float4*)&Bl[k][nq] = l;
        }
        __syncthreads();
        #pragma unroll
        for (int ks = 0; ks < 4; ks++) {
            float a[2][4], al[2][4];
            #pragma unroll
            for (int mt = 0; mt < 2; mt++) {
                int r = warp * 32 + mt * 16;
                a[mt][0] = As[r + gid][ks * 8 + tig];
                a[mt][1] = As[r + gid + 8][ks * 8 + tig];
                a[mt][2] = As[r + gid][ks * 8 + tig + 4];
                a[mt][3] = As[r + gid + 8][ks * 8 + tig + 4];
                #pragma unroll
                for (int q = 0; q < 4; q++) al[mt][q] = a[mt][q] - f32_mask13(a[mt][q]);
            }
            #pragma unroll
            for (int nt = 0; nt < 8; nt++) {
                float b0  = Bs[ks * 8 + tig][nt * 8 + gid];
                float b1  = Bs[ks * 8 + tig + 4][nt * 8 + gid];
                float bl0 = Bl[ks * 8 + tig][nt * 8 + gid];
                float bl1 = Bl[ks * 8 + tig + 4][nt * 8 + gid];
                #pragma unroll
                for (int mt = 0; mt < 2; mt++) {
                    mma_tf32(d[mt][nt], a[mt],  b0,  b1);   // hi*hi
                    mma_tf32(d[mt][nt], al[mt], b0,  b1);   // loA*hi
                    mma_tf32(d[mt][nt], a[mt],  bl0, bl1);  // hi*loB
                }
            }
        }
        __syncthreads();
    }

    float avv[8][2], aww[8][2];
    #pragma unroll
    for (int nt = 0; nt < 8; nt++) {
        avv[nt][0] = __ldg(a0 + nt * 8 + 2 * tig);
        avv[nt][1] = __ldg(a0 + nt * 8 + 2 * tig + 1);
        aww[nt][0] = __ldg(a0 + HID + nt * 8 + 2 * tig);
        aww[nt][1] = __ldg(a0 + HID + nt * 8 + 2 * tig + 1);
    }
    #pragma unroll
    for (int mt = 0; mt < 2; mt++) {
        int rloc = warp * 32 + mt * 16 + gid;
        int row0 = block_m + rloc;
        int row1 = row0 + 8;
        float prA = 0.f, pcA = 0.f, prB = 0.f, pcB = 0.f;
        #pragma unroll
        for (int nt = 0; nt < 8; nt++) {
            prA += d[mt][nt][0] * avv[nt][0] + d[mt][nt][1] * avv[nt][1];
            pcA += d[mt][nt][0] * aww[nt][0] + d[mt][nt][1] * aww[nt][1];
            prB += d[mt][nt][2] * avv[nt][0] + d[mt][nt][3] * avv[nt][1];
            pcB += d[mt][nt][2] * aww[nt][0] + d[mt][nt][3] * aww[nt][1];
            if (row0 < M)
                *(__half2*)(g_Hw0h + (size_t)row0 * HID + nt * 8 + 2 * tig) =
                    __floats2half2_rn(d[mt][nt][0], d[mt][nt][1]);
            if (row1 < M)
                *(__half2*)(g_Hw0h + (size_t)row1 * HID + nt * 8 + 2 * tig) =
                    __floats2half2_rn(d[mt][nt][2], d[mt][nt][3]);
        }
        #pragma unroll
        for (int o = 2; o; o >>= 1) {
            prA += __shfl_down_sync(0xffffffffu, prA, o, 4);
            pcA += __shfl_down_sync(0xffffffffu, pcA, o, 4);
            prB += __shfl_down_sync(0xffffffffu, prB, o, 4);
            pcB += __shfl_down_sync(0xffffffffu, pcB, o, 4);
        }
        if (tig == 0) {
            if (row0 < M) { g_pr0[row0] = prA; g_pc0[row0] = pcA; }
            if (row1 < M) { g_pr0[row1] = prB; g_pc0[row1] = pcB; }
        }
    }
}

// ---------------- scan: exclusive prefix over g_cnt -> g_rowptr; re-zeroes g_cnt ----------------
__global__ void scan_kernel(int n) {
    __shared__ int wsum[32];
    __shared__ int s_carry;
    int tid = threadIdx.x, lane = tid & 31, wid = tid >> 5;
    if (tid == 0) s_carry = 0;
    __syncthreads();
    int4* cnt4 = (int4*)g_cnt;
    int n4 = (n + 3) >> 2;
    for (int base = 0; base < n4; base += 1024) {
        int i = base + tid;
        int4 v = make_int4(0, 0, 0, 0);
        if (i < n4) {
            v = cnt4[i];
            cnt4[i] = make_int4(0, 0, 0, 0);
        }
        int s1 = v.x + v.y, s2 = s1 + v.z, s3 = s2 + v.w;
        int x = s3;
        #pragma unroll
        for (int o = 1; o < 32; o <<= 1) {
            int y = __shfl_up_sync(0xffffffffu, x, o);
            if (lane >= o) x += y;
        }
        if (lane == 31) wsum[wid] = x;
        __syncthreads();
        if (wid == 0) {
            int w = wsum[lane];
            #pragma unroll
            for (int o = 1; o < 32; o <<= 1) {
                int y = __shfl_up_sync(0xffffffffu, w, o);
                if (lane >= o) w += y;
            }
            wsum[lane] = w;
        }
        __syncthreads();
        int off = s_carry + (wid > 0 ? wsum[wid - 1] : 0) + (x - s3);
        if (i < n4) {
            int idx = i * 4;
            g_rowptr[idx]     = off;
            g_rowptr[idx + 1] = off + v.x;
            g_rowptr[idx + 2] = off + s1;
            g_rowptr[idx + 3] = off + s2;
        }
        __syncthreads();
        if (tid == 0) s_carry += wsum[31];
        __syncthreads();
    }
    if (tid == 0) g_rowptr[n] = s_carry;
}

// ---------------- atomic-free scatter using precomputed positions ----------------
__global__ void scatter_na_kernel(const int* __restrict__ ei, int E) {
    int t = blockIdx.x * blockDim.x + threadIdx.x;
    int e = t * 4;
    if (e + 3 < E) {
        int4 r = *(const int4*)(ei + e);
        int4 p = *(const int4*)(g_pos + e);
        int4 c = *(const int4*)(ei + E + e);
        g_col[g_rowptr[r.x] + p.x] = c.x;
        g_col[g_rowptr[r.y] + p.y] = c.y;
        g_col[g_rowptr[r.z] + p.z] = c.z;
        g_col[g_rowptr[r.w] + p.w] = c.w;
    } else {
        for (int j = e; j < E; j++)
            g_col[g_rowptr[ei[j]] + g_pos[j]] = ei[E + j];
    }
}

// ---------------- layer-0: fused softmax+aggregate+ELU+GEMM1+pr1/pc1, warp/row ----------------
__global__ __launch_bounds__(256) void agg64_kernel(
    const float* __restrict__ W1, const float* __restrict__ a1, int n)
{
    __shared__ float Ws[HID * OUTD];   // 4KB, W1 row-major [64][16]
    __shared__ float a1s[2 * OUTD];
    int tid = threadIdx.x;
    ((float4*)Ws)[tid] = ((const float4*)W1)[tid];   // 256*4 = 1024 floats
    if (tid < 2 * OUTD) a1s[tid] = a1[tid];
    __syncthreads();

    int w = (blockIdx.x * blockDim.x + tid) >> 5;
    int lane = tid & 31;
    if (w >= n) return;
    int s = g_rowptr[w], e = g_rowptr[w + 1];
    float prr = g_pr0[w];
    int sub = lane >> 3;    // edge slot within group of 4
    int dk  = lane & 7;     // 16-byte chunk of the 128-byte fp16 row
    const uint4* H4 = (const uint4*)g_Hw0h;
    float2 a01 = {0.f,0.f}, a23 = {0.f,0.f}, a45 = {0.f,0.f}, a67 = {0.f,0.f};
    float denom = 0.f;
    for (int base = s; base < e; base += 32) {
        int j = base + lane;
        float ev = 0.f; int c = 0;
        if (j < e) {
            c = g_col[j];
            float sc = prr + g_pc0[c];
            sc = (sc >= 0.f) ? sc : NEG_SLOPE * sc;
            ev = __expf(sc);
            denom += ev;
        }
        int cnt = min(32, e - base);
        int ng = (cnt + 3) >> 2;
        for (int t = 0; t < ng; t++) {
            int idx = t * 4 + sub;
            float ee = __shfl_sync(0xffffffffu, ev, idx);  // 0 for invalid edges
            int   cc = __shfl_sync(0xffffffffu, c, idx);
            uint4 hv = H4[(size_t)cc * 8 + dk];
            float2 e2 = make_float2(ee, ee);
            ffma2(a01, e2, __half22float2(*(__half2*)&hv.x));
            ffma2(a23, e2, __half22float2(*(__half2*)&hv.y));
            ffma2(a45, e2, __half22float2(*(__half2*)&hv.z));
            ffma2(a67, e2, __half22float2(*(__half2*)&hv.w));
        }
    }
    #pragma unroll
    for (int o = 16; o; o >>= 1) denom += __shfl_xor_sync(0xffffffffu, denom, o);
    float acc[8] = {a01.x, a01.y, a23.x, a23.y, a45.x, a45.y, a67.x, a67.y};
    #pragma unroll
    for (int o = 8; o <= 16; o <<= 1)
        #pragma unroll
        for (int i = 0; i < 8; i++)
            acc[i] += __shfl_xor_sync(0xffffffffu, acc[i], o);
    float inv = (e > s) ? 1.0f / denom : 0.0f;
    // every lane now has dims [dk*8, dk*8+8) of the H row (replicated 4x over sub)
    float h8[8];
    #pragma unroll
    for (int i = 0; i < 8; i++) {
        float v = acc[i] * inv;
        h8[i] = (v > 0.f) ? v : expm1f(v);   // ELU
    }
    // ---- fused GEMM1: replica rep = lane>>3 computes outputs [rep*4, rep*4+4) ----
    int rep = lane >> 3;
    float2 s01 = {0.f,0.f}, s23 = {0.f,0.f};
    #pragma unroll
    for (int k = 0; k < 8; k++) {
        float hk = h8[k];
        float2 h2 = make_float2(hk, hk);
        const float* wrow = Ws + (dk * 8 + k) * OUTD + rep * 4;
        ffma2(s01, h2, *(const float2*)(wrow));
        ffma2(s23, h2, *(const float2*)(wrow + 2));
    }
    // reduce over the 8 dk-lanes within each replica
    #pragma unroll
    for (int o = 4; o; o >>= 1) {
        s01.x += __shfl_xor_sync(0xffffffffu, s01.x, o);
        s01.y += __shfl_xor_sync(0xffffffffu, s01.y, o);
        s23.x += __shfl_xor_sync(0xffffffffu, s23.x, o);
        s23.y += __shfl_xor_sync(0xffffffffu, s23.y, o);
    }
    // pr1/pc1 partials over this replica's 4 outputs
    float pr = s01.x * a1s[rep*4] + s01.y * a1s[rep*4+1]
             + s23.x * a1s[rep*4+2] + s23.y * a1s[rep*4+3];
    float pc = s01.x * a1s[OUTD+rep*4] + s01.y * a1s[OUTD+rep*4+1]
             + s23.x * a1s[OUTD+rep*4+2] + s23.y * a1s[OUTD+rep*4+3];
    pr += __shfl_xor_sync(0xffffffffu, pr, 8);
    pr += __shfl_xor_sync(0xffffffffu, pr, 16);
    pc += __shfl_xor_sync(0xffffffffu, pc, 8);
    pc += __shfl_xor_sync(0xffffffffu, pc, 16);
    if (dk == 0) {
        __half2 h0 = __floats2half2_rn(s01.x, s01.y);
        __half2 h1 = __floats2half2_rn(s23.x, s23.y);
        uint2 u;
        u.x = *(unsigned int*)&h0;
        u.y = *(unsigned int*)&h1;
        *(uint2*)(g_Hw1h + (size_t)w * OUTD + rep * 4) = u;   // 8B aligned
    }
    if (lane == 0) { g_pr1[w] = pr; g_pc1[w] = pc; }
}

// ---------------- layer-1 fused softmax+aggregate (D=16, fp16) + log_softmax ----------------
__global__ __launch_bounds__(256) void agg16_kernel(float* __restrict__ out, int n) {
    int w = (blockIdx.x * blockDim.x + threadIdx.x) >> 5;
    int lane = threadIdx.x & 31;
    if (w >= n) return;
    int s = g_rowptr[w], e = g_rowptr[w + 1];
    float prr = g_pr1[w];
    int sub = lane >> 1;     // edge within group of 16
    int dk  = lane & 1;      // which 16-byte half of the 32-byte fp16 row
    const uint4* H4 = (const uint4*)g_Hw1h;
    float2 a01 = {0.f,0.f}, a23 = {0.f,0.f}, a45 = {0.f,0.f}, a67 = {0.f,0.f};
    float denom = 0.f;
    for (int base = s; base < e; base += 32) {
        int j = base + lane;
        float ev = 0.f; int c = 0;
        if (j < e) {
            c = g_col[j];
            float sc = prr + g_pc1[c];
            sc = (sc >= 0.f) ? sc : NEG_SLOPE * sc;
            ev = __expf(sc);
            denom += ev;
        }
        int cnt = min(32, e - base);
        int ng = (cnt + 15) >> 4;
        for (int t = 0; t < ng; t++) {
            int idx = t * 16 + sub;
            float ee = __shfl_sync(0xffffffffu, ev, idx);
            int   cc = __shfl_sync(0xffffffffu, c, idx);
            uint4 hv = H4[(size_t)cc * 2 + dk];
            float2 e2 = make_float2(ee, ee);
            ffma2(a01, e2, __half22float2(*(__half2*)&hv.x));
            ffma2(a23, e2, __half22float2(*(__half2*)&hv.y));
            ffma2(a45, e2, __half22float2(*(__half2*)&hv.z));
            ffma2(a67, e2, __half22float2(*(__half2*)&hv.w));
        }
    }
    #pragma unroll
    for (int o = 16; o; o >>= 1) denom += __shfl_xor_sync(0xffffffffu, denom, o);
    float acc[8] = {a01.x, a01.y, a23.x, a23.y, a45.x, a45.y, a67.x, a67.y};
    #pragma unroll
    for (int o = 2; o <= 16; o <<= 1)
        #pragma unroll
        for (int i = 0; i < 8; i++)
            acc[i] += __shfl_xor_sync(0xffffffffu, acc[i], o);
    float inv = (e > s) ? 1.0f / denom : 0.0f;
    float v[8];
    #pragma unroll
    for (int i = 0; i < 8; i++) v[i] = acc[i] * inv;
    float m = v[0];
    #pragma unroll
    for (int i = 1; i < 8; i++) m = fmaxf(m, v[i]);
    m = fmaxf(m, __shfl_xor_sync(0xffffffffu, m, 1));
    float se = 0.f;
    #pragma unroll
    for (int i = 0; i < 8; i++) se += __expf(v[i] - m);
    se += __shfl_xor_sync(0xffffffffu, se, 1);
    float l = m + logf(se);
    if (lane < 2) {
        float* dst = out + (size_t)w * OUTD + dk * 8;
        *(float4*)(dst)     = make_float4(v[0] - l, v[1] - l, v[2] - l, v[3] - l);
        *(float4*)(dst + 4) = make_float4(v[4] - l, v[5] - l, v[6] - l, v[7] - l);
    }
}

// ---------------- launch ----------------
extern "C" void kernel_launch(void* const* d_in, const int* in_sizes, int n_in,
                              void* d_out, int out_size) {
    const float* X  = (const float*)d_in[0];
    const int*   ei = (const int*)  d_in[1];
    const float* W0 = (const float*)d_in[2];
    const float* a0 = (const float*)d_in[3];
    const float* W1 = (const float*)d_in[4];
    const float* a1 = (const float*)d_in[5];
    float* out = (float*)d_out;

    int N = in_sizes[0] / IN_DIM;
    int E = in_sizes[1] / 2;

    int nCountBlks = (E + EDGES_PER_BLK - 1) / EDGES_PER_BLK;
    int nGemmBlks  = (N + GBM - 1) / GBM;

    fat_kernel<<<nCountBlks + nGemmBlks, 128>>>(X, W0, a0, ei, N, E, nCountBlks);
    scan_kernel<<<1, 1024>>>(N);
    scatter_na_kernel<<<(E / 4 + 255) / 256, 256>>>(ei, E);

    // layer 0 aggregate + ELU + fused gemm1 + pr1/pc1
    agg64_kernel<<<(N + 7) / 8, 256>>>(W1, a1, N);

    // layer 1 aggregate + log-softmax
    agg16_kernel<<<(N + 7) / 8, 256>>>(out, N);
}

// round 8
// speedup vs baseline: 1.1480x; 1.1480x over previous
#include <cuda_runtime.h>
#include <cuda_fp16.h>
#include <cuda_bf16.h>
#include <math.h>

// ---------------- problem constants ----------------
#define IN_DIM 256
#define HID 64
#define OUTD 16
#define NEG_SLOPE 0.01f

#define MAXN 50048
#define MAXE 1600000

// ---------------- device scratch (static, no allocs; zero-init at load) ----------------
__device__ __align__(16) __half g_Hw0h[(size_t)MAXN * HID]; // X @ W0 (fp16 for gather)
__device__ __align__(16) __half g_Hw1h[(size_t)MAXN * OUTD];// layer-1 features (fp16)
__device__ float g_pr0[MAXN], g_pc0[MAXN];
__device__ float g_pr1[MAXN], g_pc1[MAXN];
__device__ __align__(16) int g_cnt[MAXN];   // zero at load; scan re-zeroes each run
__device__ int   g_rowptr[MAXN + 1];
__device__ __align__(16) int g_pos[MAXE];
__device__ int   g_col[MAXE];

// ---------------- tf32 MMA helpers ----------------
__device__ __forceinline__ float f32_mask13(float x) {
    return __uint_as_float(__float_as_uint(x) & 0xFFFFE000u);
}
__device__ __forceinline__ void mma_tf32(float d[4], const float a[4], float b0, float b1) {
    asm volatile(
        "mma.sync.aligned.m16n8k8.row.col.f32.tf32.tf32.f32 "
        "{%0,%1,%2,%3}, {%4,%5,%6,%7}, {%8,%9}, {%0,%1,%2,%3};\n"
        : "+f"(d[0]), "+f"(d[1]), "+f"(d[2]), "+f"(d[3])
        : "r"(__float_as_uint(a[0])), "r"(__float_as_uint(a[1])),
          "r"(__float_as_uint(a[2])), "r"(__float_as_uint(a[3])),
          "r"(__float_as_uint(b0)), "r"(__float_as_uint(b1)));
}

// ---------------- FAT kernel: count_pos blocks + gemm0 blocks ----------------
#define GBM 128
#define EDGES_PER_BLK 1024

__global__ __launch_bounds__(128) void fat_kernel(
    const float* __restrict__ X, const float* __restrict__ W,
    const float* __restrict__ a0, const int* __restrict__ ei,
    int M, int E, int nCountBlks)
{
    __shared__ float As[GBM][36];
    __shared__ float Bs[32][64];
    __shared__ float Bl[32][64];

    int tid = threadIdx.x;

    if ((int)blockIdx.x < nCountBlks) {
        int base = blockIdx.x * EDGES_PER_BLK;
        #pragma unroll
        for (int h = 0; h < 2; h++) {
            int e = base + h * 512 + tid * 4;
            if (e + 3 < E) {
                int4 r = *(const int4*)(ei + e);
                int4 p;
                p.x = atomicAdd(&g_cnt[r.x], 1);
                p.y = atomicAdd(&g_cnt[r.y], 1);
                p.z = atomicAdd(&g_cnt[r.z], 1);
                p.w = atomicAdd(&g_cnt[r.w], 1);
                *(int4*)(g_pos + e) = p;
            } else {
                for (int j = e; j < E; j++) g_pos[j] = atomicAdd(&g_cnt[ei[j]], 1);
            }
        }
        return;
    }

    int lane = tid & 31, warp = tid >> 5;
    int gid = lane >> 2, tig = lane & 3;
    int block_m = (blockIdx.x - nCountBlks) * GBM;

    float d[2][8][4];
    #pragma unroll
    for (int mt = 0; mt < 2; mt++)
        #pragma unroll
        for (int nt = 0; nt < 8; nt++)
            #pragma unroll
            for (int q = 0; q < 4; q++) d[mt][nt][q] = 0.f;

    for (int k0 = 0; k0 < IN_DIM; k0 += 32) {
        #pragma unroll
        for (int i = 0; i < 8; i++) {
            int f = tid + 128 * i;
            int row = f >> 3, q = (f & 7) * 4;
            int gm = block_m + row;
            float4 v = (gm < M) ? *(const float4*)(X + (size_t)gm * IN_DIM + k0 + q)
                                : make_float4(0.f, 0.f, 0.f, 0.f);
            *(float4*)&As[row][q] = v;
        }
        #pragma unroll
        for (int i = 0; i < 4; i++) {
            int f = tid + 128 * i;
            int k = f >> 4, nq = (f & 15) * 4;
            float4 v = *(const float4*)(W + (size_t)(k0 + k) * HID + nq);
            float4 l;
            l.x = v.x - f32_mask13(v.x);
            l.y = v.y - f32_mask13(v.y);
            l.z = v.z - f32_mask13(v.z);
            l.w = v.w - f32_mask13(v.w);
            *(float4*)&Bs[k][nq] = v;
            *(float4*)&Bl[k][nq] = l;
        }
        __syncthreads();
        #pragma unroll
        for (int ks = 0; ks < 4; ks++) {
            float a[2][4], al[2][4];
            #pragma unroll
            for (int mt = 0; mt < 2; mt++) {
                int r = warp * 32 + mt * 16;
                a[mt][0] = As[r + gid][ks * 8 + tig];
                a[mt][1] = As[r + gid + 8][ks * 8 + tig];
                a[mt][2] = As[r + gid][ks * 8 + tig + 4];
                a[mt][3] = As[r + gid + 8][ks * 8 + tig + 4];
                #pragma unroll
                for (int q = 0; q < 4; q++) al[mt][q] = a[mt][q] - f32_mask13(a[mt][q]);
            }
            #pragma unroll
            for (int nt = 0; nt < 8; nt++) {
                float b0  = Bs[ks * 8 + tig][nt * 8 + gid];
                float b1  = Bs[ks * 8 + tig + 4][nt * 8 + gid];
                float bl0 = Bl[ks * 8 + tig][nt * 8 + gid];
                float bl1 = Bl[ks * 8 + tig + 4][nt * 8 + gid];
                #pragma unroll
                for (int mt = 0; mt < 2; mt++) {
                    mma_tf32(d[mt][nt], a[mt],  b0,  b1);   // hi*hi
                    mma_tf32(d[mt][nt], al[mt], b0,  b1);   // loA*hi
                    mma_tf32(d[mt][nt], a[mt],  bl0, bl1);  // hi*loB
                }
            }
        }
        __syncthreads();
    }

    float avv[8][2], aww[8][2];
    #pragma unroll
    for (int nt = 0; nt < 8; nt++) {
        avv[nt][0] = __ldg(a0 + nt * 8 + 2 * tig);
        avv[nt][1] = __ldg(a0 + nt * 8 + 2 * tig + 1);
        aww[nt][0] = __ldg(a0 + HID + nt * 8 + 2 * tig);
        aww[nt][1] = __ldg(a0 + HID + nt * 8 + 2 * tig + 1);
    }
    #pragma unroll
    for (int mt = 0; mt < 2; mt++) {
        int rloc = warp * 32 + mt * 16 + gid;
        int row0 = block_m + rloc;
        int row1 = row0 + 8;
        float prA = 0.f, pcA = 0.f, prB = 0.f, pcB = 0.f;
        #pragma unroll
        for (int nt = 0; nt < 8; nt++) {
            prA += d[mt][nt][0] * avv[nt][0] + d[mt][nt][1] * avv[nt][1];
            pcA += d[mt][nt][0] * aww[nt][0] + d[mt][nt][1] * aww[nt][1];
            prB += d[mt][nt][2] * avv[nt][0] + d[mt][nt][3] * avv[nt][1];
            pcB += d[mt][nt][2] * aww[nt][0] + d[mt][nt][3] * aww[nt][1];
            if (row0 < M)
                *(__half2*)(g_Hw0h + (size_t)row0 * HID + nt * 8 + 2 * tig) =
                    __floats2half2_rn(d[mt][nt][0], d[mt][nt][1]);
            if (row1 < M)
                *(__half2*)(g_Hw0h + (size_t)row1 * HID + nt * 8 + 2 * tig) =
                    __floats2half2_rn(d[mt][nt][2], d[mt][nt][3]);
        }
        #pragma unroll
        for (int o = 2; o; o >>= 1) {
            prA += __shfl_down_sync(0xffffffffu, prA, o, 4);
            pcA += __shfl_down_sync(0xffffffffu, pcA, o, 4);
            prB += __shfl_down_sync(0xffffffffu, prB, o, 4);
            pcB += __shfl_down_sync(0xffffffffu, pcB, o, 4);
        }
        if (tig == 0) {
            if (row0 < M) { g_pr0[row0] = prA; g_pc0[row0] = pcA; }
            if (row1 < M) { g_pr0[row1] = prB; g_pc0[row1] = pcB; }
        }
    }
}

// ---------------- scan: exclusive prefix over g_cnt -> g_rowptr; re-zeroes g_cnt ----------------
__global__ void scan_kernel(int n) {
    __shared__ int wsum[32];
    __shared__ int s_carry;
    int tid = threadIdx.x, lane = tid & 31, wid = tid >> 5;
    if (tid == 0) s_carry = 0;
    __syncthreads();
    int4* cnt4 = (int4*)g_cnt;
    int n4 = (n + 3) >> 2;
    for (int base = 0; base < n4; base += 1024) {
        int i = base + tid;
        int4 v = make_int4(0, 0, 0, 0);
        if (i < n4) {
            v = cnt4[i];
            cnt4[i] = make_int4(0, 0, 0, 0);
        }
        int s1 = v.x + v.y, s2 = s1 + v.z, s3 = s2 + v.w;
        int x = s3;
        #pragma unroll
        for (int o = 1; o < 32; o <<= 1) {
            int y = __shfl_up_sync(0xffffffffu, x, o);
            if (lane >= o) x += y;
        }
        if (lane == 31) wsum[wid] = x;
        __syncthreads();
        if (wid == 0) {
            int w = wsum[lane];
            #pragma unroll
            for (int o = 1; o < 32; o <<= 1) {
                int y = __shfl_up_sync(0xffffffffu, w, o);
                if (lane >= o) w += y;
            }
            wsum[lane] = w;
        }
        __syncthreads();
        int off = s_carry + (wid > 0 ? wsum[wid - 1] : 0) + (x - s3);
        if (i < n4) {
            int idx = i * 4;
            g_rowptr[idx]     = off;
            g_rowptr[idx + 1] = off + v.x;
            g_rowptr[idx + 2] = off + s1;
            g_rowptr[idx + 3] = off + s2;
        }
        __syncthreads();
        if (tid == 0) s_carry += wsum[31];
        __syncthreads();
    }
    if (tid == 0) g_rowptr[n] = s_carry;
}

// ---------------- atomic-free scatter using precomputed positions ----------------
__global__ void scatter_na_kernel(const int* __restrict__ ei, int E) {
    int t = blockIdx.x * blockDim.x + threadIdx.x;
    int e = t * 4;
    if (e + 3 < E) {
        int4 r = *(const int4*)(ei + e);
        int4 p = *(const int4*)(g_pos + e);
        int4 c = *(const int4*)(ei + E + e);
        g_col[g_rowptr[r.x] + p.x] = c.x;
        g_col[g_rowptr[r.y] + p.y] = c.y;
        g_col[g_rowptr[r.z] + p.z] = c.z;
        g_col[g_rowptr[r.w] + p.w] = c.w;
    } else {
        for (int j = e; j < E; j++)
            g_col[g_rowptr[ei[j]] + g_pos[j]] = ei[E + j];
    }
}

// ---------------- layer-0: softmax+aggregate+ELU+GEMM1+pr1/pc1 fused, warp/row ----------------
// W1 staged in smem at p(k,o) = (k&7)*160 + o*10 + (k>>3) so the epilogue's
// 32-lane LDS pattern hits bank (8*sub + 10*q + dk) mod 32 -> conflict-free.
__global__ __launch_bounds__(256) void agg64_kernel(
    const float* __restrict__ W1, const float* __restrict__ a1, int n)
{
    __shared__ float Ws[1280];         // 5KB swizzled W1
    __shared__ float a1s[2 * OUTD];
    int tid = threadIdx.x;
    #pragma unroll
    for (int i = 0; i < 4; i++) {
        int idx = tid + 256 * i;       // 0..1023
        int k = idx >> 4, o = idx & 15;
        Ws[(k & 7) * 160 + o * 10 + (k >> 3)] = W1[idx];
    }
    if (tid < 2 * OUTD) a1s[tid] = a1[tid];
    __syncthreads();

    int w = (blockIdx.x * blockDim.x + tid) >> 5;
    int lane = tid & 31;
    if (w >= n) return;
    int s = g_rowptr[w], e = g_rowptr[w + 1];
    float prr = g_pr0[w];
    int sub = lane >> 3;    // edge slot within group of 4
    int dk  = lane & 7;     // 16-byte chunk of the 128-byte fp16 row
    const uint4* H4 = (const uint4*)g_Hw0h;
    float acc[8] = {0.f, 0.f, 0.f, 0.f, 0.f, 0.f, 0.f, 0.f};
    float denom = 0.f;
    for (int base = s; base < e; base += 32) {
        int j = base + lane;
        float ev = 0.f; int c = 0;
        if (j < e) {
            c = g_col[j];
            float sc = prr + g_pc0[c];
            sc = (sc >= 0.f) ? sc : NEG_SLOPE * sc;
            ev = __expf(sc);
            denom += ev;
        }
        int cnt = min(32, e - base);
        int ng = (cnt + 3) >> 2;
        for (int t = 0; t < ng; t++) {
            int idx = t * 4 + sub;
            float ee = __shfl_sync(0xffffffffu, ev, idx);  // 0 for invalid edges
            int   cc = __shfl_sync(0xffffffffu, c, idx);
            uint4 hv = H4[(size_t)cc * 8 + dk];
            float2 f0 = __half22float2(*(__half2*)&hv.x);
            float2 f1 = __half22float2(*(__half2*)&hv.y);
            float2 f2 = __half22float2(*(__half2*)&hv.z);
            float2 f3 = __half22float2(*(__half2*)&hv.w);
            acc[0] += ee * f0.x; acc[1] += ee * f0.y;
            acc[2] += ee * f1.x; acc[3] += ee * f1.y;
            acc[4] += ee * f2.x; acc[5] += ee * f2.y;
            acc[6] += ee * f3.x; acc[7] += ee * f3.y;
        }
    }
    #pragma unroll
    for (int o = 16; o; o >>= 1) denom += __shfl_xor_sync(0xffffffffu, denom, o);
    #pragma unroll
    for (int o = 8; o <= 16; o <<= 1)
        #pragma unroll
        for (int i = 0; i < 8; i++)
            acc[i] += __shfl_xor_sync(0xffffffffu, acc[i], o);
    float inv = (e > s) ? 1.0f / denom : 0.0f;
    // lane has dims [dk*8, dk*8+8) of H row, replicated 4x over sub
    float h8[8];
    #pragma unroll
    for (int i = 0; i < 8; i++) {
        float v = acc[i] * inv;
        h8[i] = (v > 0.f) ? v : expm1f(v);   // ELU
    }
    // fused GEMM1: lane (sub,dk) -> partial of outputs [sub*4, sub*4+4) over dims dk*8..+8
    float so[4] = {0.f, 0.f, 0.f, 0.f};
    #pragma unroll
    for (int i = 0; i < 8; i++) {
        const float* wp = Ws + i * 160 + dk;
        float hk = h8[i];
        #pragma unroll
        for (int q = 0; q < 4; q++)
            so[q] += hk * wp[(sub * 4 + q) * 10];   // conflict-free LDS
    }
    // reduce over dk (lane bits 0..2)
    #pragma unroll
    for (int o = 4; o; o >>= 1)
        #pragma unroll
        for (int q = 0; q < 4; q++)
            so[q] += __shfl_xor_sync(0xffffffffu, so[q], o);
    // pr1/pc1 partials over this sub's 4 outputs
    float pr = so[0]*a1s[sub*4] + so[1]*a1s[sub*4+1] + so[2]*a1s[sub*4+2] + so[3]*a1s[sub*4+3];
    float pc = so[0]*a1s[OUTD+sub*4] + so[1]*a1s[OUTD+sub*4+1]
             + so[2]*a1s[OUTD+sub*4+2] + so[3]*a1s[OUTD+sub*4+3];
    pr += __shfl_xor_sync(0xffffffffu, pr, 8);
    pr += __shfl_xor_sync(0xffffffffu, pr, 16);
    pc += __shfl_xor_sync(0xffffffffu, pc, 8);
    pc += __shfl_xor_sync(0xffffffffu, pc, 16);
    if (dk == 0) {
        __half2 h0 = __floats2half2_rn(so[0], so[1]);
        __half2 h1 = __floats2half2_rn(so[2], so[3]);
        uint2 u;
        u.x = *(unsigned int*)&h0;
        u.y = *(unsigned int*)&h1;
        *(uint2*)(g_Hw1h + (size_t)w * OUTD + sub * 4) = u;   // 8B aligned
    }
    if (lane == 0) { g_pr1[w] = pr; g_pc1[w] = pc; }
}

// ---------------- layer-1 fused softmax+aggregate (D=16, fp16) + log_softmax ----------------
__global__ __launch_bounds__(256) void agg16_kernel(float* __restrict__ out, int n) {
    int w = (blockIdx.x * blockDim.x + threadIdx.x) >> 5;
    int lane = threadIdx.x & 31;
    if (w >= n) return;
    int s = g_rowptr[w], e = g_rowptr[w + 1];
    float prr = g_pr1[w];
    int sub = lane >> 1;     // edge within group of 16
    int dk  = lane & 1;      // which 16-byte half of the 32-byte fp16 row
    const uint4* H4 = (const uint4*)g_Hw1h;
    float acc[8] = {0.f, 0.f, 0.f, 0.f, 0.f, 0.f, 0.f, 0.f};
    float denom = 0.f;
    for (int base = s; base < e; base += 32) {
        int j = base + lane;
        float ev = 0.f; int c = 0;
        if (j < e) {
            c = g_col[j];
            float sc = prr + g_pc1[c];
            sc = (sc >= 0.f) ? sc : NEG_SLOPE * sc;
            ev = __expf(sc);
            denom += ev;
        }
        int cnt = min(32, e - base);
        int ng = (cnt + 15) >> 4;
        for (int t = 0; t < ng; t++) {
            int idx = t * 16 + sub;
            float ee = __shfl_sync(0xffffffffu, ev, idx);
            int   cc = __shfl_sync(0xffffffffu, c, idx);
            uint4 hv = H4[(size_t)cc * 2 + dk];
            float2 f0 = __half22float2(*(__half2*)&hv.x);
            float2 f1 = __half22float2(*(__half2*)&hv.y);
            float2 f2 = __half22float2(*(__half2*)&hv.z);
            float2 f3 = __half22float2(*(__half2*)&hv.w);
            acc[0] += ee * f0.x; acc[1] += ee * f0.y;
            acc[2] += ee * f1.x; acc[3] += ee * f1.y;
            acc[4] += ee * f2.x; acc[5] += ee * f2.y;
            acc[6] += ee * f3.x; acc[7] += ee * f3.y;
        }
    }
    #pragma unroll
    for (int o = 16; o; o >>= 1) denom += __shfl_xor_sync(0xffffffffu, denom, o);
    #pragma unroll
    for (int o = 2; o <= 16; o <<= 1)
        #pragma unroll
        for (int i = 0; i < 8; i++)
            acc[i] += __shfl_xor_sync(0xffffffffu, acc[i], o);
    float inv = (e > s) ? 1.0f / denom : 0.0f;
    float v[8];
    #pragma unroll
    for (int i = 0; i < 8; i++) v[i] = acc[i] * inv;
    float m = v[0];
    #pragma unroll
    for (int i = 1; i < 8; i++) m = fmaxf(m, v[i]);
    m = fmaxf(m, __shfl_xor_sync(0xffffffffu, m, 1));
    float se = 0.f;
    #pragma unroll
    for (int i = 0; i < 8; i++) se += __expf(v[i] - m);
    se += __shfl_xor_sync(0xffffffffu, se, 1);
    float l = m + logf(se);
    if (lane < 2) {
        float* dst = out + (size_t)w * OUTD + dk * 8;
        *(float4*)(dst)     = make_float4(v[0] - l, v[1] - l, v[2] - l, v[3] - l);
        *(float4*)(dst + 4) = make_float4(v[4] - l, v[5] - l, v[6] - l, v[7] - l);
    }
}

// ---------------- launch ----------------
extern "C" void kernel_launch(void* const* d_in, const int* in_sizes, int n_in,
                              void* d_out, int out_size) {
    const float* X  = (const float*)d_in[0];
    const int*   ei = (const int*)  d_in[1];
    const float* W0 = (const float*)d_in[2];
    const float* a0 = (const float*)d_in[3];
    const float* W1 = (const float*)d_in[4];
    const float* a1 = (const float*)d_in[5];
    float* out = (float*)d_out;

    int N = in_sizes[0] / IN_DIM;
    int E = in_sizes[1] / 2;

    int nCountBlks = (E + EDGES_PER_BLK - 1) / EDGES_PER_BLK;
    int nGemmBlks  = (N + GBM - 1) / GBM;

    fat_kernel<<<nCountBlks + nGemmBlks, 128>>>(X, W0, a0, ei, N, E, nCountBlks);
    scan_kernel<<<1, 1024>>>(N);
    scatter_na_kernel<<<(E / 4 + 255) / 256, 256>>>(ei, E);

    // layer 0 aggregate + ELU + fused gemm1 + pr1/pc1
    agg64_kernel<<<(N + 7) / 8, 256>>>(W1, a1, N);

    // layer 1 aggregate + log-softmax
    agg16_kernel<<<(N + 7) / 8, 256>>>(out, N);
}